// round 1
// baseline (speedup 1.0000x reference)
#include <cuda_runtime.h>
#include <cstdint>

// LSTM: N=64 batch, T=512 steps, D=1024 in, H=1024 hidden, G=4H=4096 gates.
// Phase A: xW[m, g] = x[m,:] @ Wx + b   (m = n*T + t), 32768x4096x1024 fp32 GEMM.
// Phase B: 512 sequential step kernels: a = xW[:,t,:] + h @ Wh ; gates ; c,h update.
// All math fp32; fp32 throughput doubled via packed fma.rn.f32x2 (FFMA2).

#define N_  64
#define T_  512
#define D_  1024
#define H_  1024
#define G_  4096
#define M_  (N_ * T_)   // 32768

// Scratch: device globals (no runtime allocation allowed).
static __device__ __align__(16) float g_xw[(size_t)M_ * G_];   // 512 MB
static __device__ __align__(16) float g_h[2][N_ * H_];         // h ping-pong
static __device__ __align__(16) float g_c[N_ * H_];            // cell state

// ---------- packed f32x2 helpers (FFMA2: 2x fp32 FMA throughput) ----------
__device__ __forceinline__ unsigned long long pack2(float x, float y) {
    unsigned long long r;
    asm("mov.b64 %0, {%1, %2};" : "=l"(r) : "f"(x), "f"(y));
    return r;
}
__device__ __forceinline__ void unpack2(unsigned long long v, float &x, float &y) {
    asm("mov.b64 {%0, %1}, %2;" : "=f"(x), "=f"(y) : "l"(v));
}
__device__ __forceinline__ void ffma2(unsigned long long &c,
                                      unsigned long long a,
                                      unsigned long long b) {
    asm("fma.rn.f32x2 %0, %1, %2, %0;" : "+l"(c) : "l"(a), "l"(b));
}

__device__ __forceinline__ float sigmoidf_(float x) {
    return 1.0f / (1.0f + __expf(-x));
}

// ---------------- init: h = h0, c = 0 ----------------
__global__ void init_kernel(const float* __restrict__ h0) {
    int i = blockIdx.x * blockDim.x + threadIdx.x;
    if (i < N_ * H_) {
        g_h[0][i] = h0[i];
        g_c[i] = 0.0f;
    }
}

// ---------------- Phase A: xW = x @ Wx + b ----------------
// 128x128x8 tile, 256 threads, 8x8 per-thread (as 8x4 f32x2), double-buffered smem.
__global__ __launch_bounds__(256, 2)
void gemm_xw_kernel(const float* __restrict__ X,
                    const float* __restrict__ Wx,
                    const float* __restrict__ bias) {
    __shared__ __align__(16) float As[2][8][132];  // transposed A, padded
    __shared__ __align__(16) float Bs[2][8][128];

    const int tid = threadIdx.x;
    const int bx = blockIdx.x;   // N/128 = 32
    const int by = blockIdx.y;   // M/128 = 256
    const int tx = tid & 15;
    const int ty = tid >> 4;

    // global-load mapping
    const int ar = tid >> 1;             // 0..127 (A row within tile)
    const int ak = (tid & 1) * 4;        // 0 or 4 (k sub)
    const float* aptr = X + (size_t)(by * 128 + ar) * D_ + ak;
    const int bk = tid >> 5;             // 0..7
    const int bc = (tid & 31) * 4;       // 0..124
    const float* bptr = Wx + (size_t)bk * G_ + bx * 128 + bc;

    unsigned long long acc[8][4];
    #pragma unroll
    for (int i = 0; i < 8; i++)
        #pragma unroll
        for (int j = 0; j < 4; j++) acc[i][j] = 0ULL;

    float4 ra = *(const float4*)(aptr);
    float4 rb = *(const float4*)(bptr);
    As[0][ak + 0][ar] = ra.x; As[0][ak + 1][ar] = ra.y;
    As[0][ak + 2][ar] = ra.z; As[0][ak + 3][ar] = ra.w;
    *(float4*)&Bs[0][bk][bc] = rb;
    __syncthreads();

    int buf = 0;
    const int NT = D_ / 8;   // 128 tiles
    for (int kt = 0; kt < NT; kt++) {
        if (kt + 1 < NT) {
            ra = *(const float4*)(aptr + (kt + 1) * 8);
            rb = *(const float4*)(bptr + (size_t)(kt + 1) * 8 * G_);
        }
        #pragma unroll
        for (int k = 0; k < 8; k++) {
            float4 a0 = *(const float4*)&As[buf][k][ty * 8];
            float4 a1 = *(const float4*)&As[buf][k][ty * 8 + 4];
            float4 b0 = *(const float4*)&Bs[buf][k][tx * 8];
            float4 b1 = *(const float4*)&Bs[buf][k][tx * 8 + 4];
            unsigned long long bp0 = pack2(b0.x, b0.y);
            unsigned long long bp1 = pack2(b0.z, b0.w);
            unsigned long long bp2 = pack2(b1.x, b1.y);
            unsigned long long bp3 = pack2(b1.z, b1.w);
            float av[8] = {a0.x, a0.y, a0.z, a0.w, a1.x, a1.y, a1.z, a1.w};
            #pragma unroll
            for (int i = 0; i < 8; i++) {
                unsigned long long ap = pack2(av[i], av[i]);
                ffma2(acc[i][0], ap, bp0);
                ffma2(acc[i][1], ap, bp1);
                ffma2(acc[i][2], ap, bp2);
                ffma2(acc[i][3], ap, bp3);
            }
        }
        if (kt + 1 < NT) {
            int nb = buf ^ 1;
            As[nb][ak + 0][ar] = ra.x; As[nb][ak + 1][ar] = ra.y;
            As[nb][ak + 2][ar] = ra.z; As[nb][ak + 3][ar] = ra.w;
            *(float4*)&Bs[nb][bk][bc] = rb;
            __syncthreads();
            buf = nb;
        }
    }

    // epilogue: + bias, store
    const int colbase = bx * 128 + tx * 8;
    float4 bb0 = *(const float4*)(bias + colbase);
    float4 bb1 = *(const float4*)(bias + colbase + 4);
    #pragma unroll
    for (int i = 0; i < 8; i++) {
        int row = by * 128 + ty * 8 + i;
        float x0, x1, x2, x3, x4, x5, x6, x7;
        unpack2(acc[i][0], x0, x1); unpack2(acc[i][1], x2, x3);
        unpack2(acc[i][2], x4, x5); unpack2(acc[i][3], x6, x7);
        float4 o0 = {x0 + bb0.x, x1 + bb0.y, x2 + bb0.z, x3 + bb0.w};
        float4 o1 = {x4 + bb1.x, x5 + bb1.y, x6 + bb1.z, x7 + bb1.w};
        float* cp = g_xw + (size_t)row * G_ + colbase;
        *(float4*)cp = o0;
        *(float4*)(cp + 4) = o1;
    }
}

// ---------------- Phase B: one recurrent step ----------------
// Block covers: all 64 batch rows x 8 gate-columns x 4 gates (grid = 128 blocks).
// GEMM a_blk = h @ Wh[:, block cols], then fused gate nonlinearity + c/h update.
__global__ __launch_bounds__(256)
void lstm_step_kernel(const float* __restrict__ Wh,
                      float* __restrict__ out,
                      int t, int pin) {
    __shared__ __align__(16) float As[2][32][66];  // h tile, transposed, padded
    __shared__ __align__(16) float Bs[2][32][32];  // Wh tile (4 gates x 8 cols)
    __shared__ __align__(16) float sm_a[64][34];   // h@Wh partial result

    const int tid = threadIdx.x;
    const int j0 = blockIdx.x * 8;        // gate-local col offset, 0..1016
    const float* hin = g_h[pin];
    float* hout = g_h[pin ^ 1];

    // A (h) load mapping: 8 scalars per thread via 2 float4 loads
    const int am = tid >> 2;              // 0..63 (batch row)
    const int ac = tid & 3;               // chunk: ac and ac+4 of 8
    // B (Wh) load mapping: 1 float4 per thread
    const int bk = tid >> 3;              // 0..31 (k row)
    const int bq = tid & 7;
    const int bg = bq >> 1;               // gate 0..3
    const int bp = (bq & 1) * 4;          // 0 or 4
    const float* bptr = Wh + (size_t)bk * G_ + bg * 1024 + j0 + bp;

    // compute mapping: 2 rows x 4 cols per thread
    const int mi = tid >> 3;              // 0..31 -> rows 2mi, 2mi+1
    const int ci = tid & 7;               // 0..7  -> cols 4ci..4ci+3

    unsigned long long acc00 = 0, acc01 = 0, acc10 = 0, acc11 = 0;

    float4 ra0 = *(const float4*)(hin + (size_t)am * H_ + ac * 4);
    float4 ra1 = *(const float4*)(hin + (size_t)am * H_ + (ac + 4) * 4);
    float4 rb  = *(const float4*)(bptr);

    {
        int k0a = ac * 4, k0b = (ac + 4) * 4;
        As[0][k0a + 0][am] = ra0.x; As[0][k0a + 1][am] = ra0.y;
        As[0][k0a + 2][am] = ra0.z; As[0][k0a + 3][am] = ra0.w;
        As[0][k0b + 0][am] = ra1.x; As[0][k0b + 1][am] = ra1.y;
        As[0][k0b + 2][am] = ra1.z; As[0][k0b + 3][am] = ra1.w;
        *(float4*)&Bs[0][bk][bg * 8 + bp] = rb;
    }
    __syncthreads();

    int buf = 0;
    const int NT = H_ / 32;   // 32 tiles
    for (int kt = 0; kt < NT; kt++) {
        if (kt + 1 < NT) {
            int k0 = (kt + 1) * 32;
            ra0 = *(const float4*)(hin + (size_t)am * H_ + k0 + ac * 4);
            ra1 = *(const float4*)(hin + (size_t)am * H_ + k0 + (ac + 4) * 4);
            rb  = *(const float4*)(bptr + (size_t)k0 * G_);
        }
        #pragma unroll
        for (int k = 0; k < 32; k++) {
            float2 av  = *(const float2*)&As[buf][k][2 * mi];
            float4 bq4 = *(const float4*)&Bs[buf][k][ci * 4];
            unsigned long long ap0 = pack2(av.x, av.x);
            unsigned long long ap1 = pack2(av.y, av.y);
            unsigned long long bv0 = pack2(bq4.x, bq4.y);
            unsigned long long bv1 = pack2(bq4.z, bq4.w);
            ffma2(acc00, ap0, bv0);
            ffma2(acc01, ap0, bv1);
            ffma2(acc10, ap1, bv0);
            ffma2(acc11, ap1, bv1);
        }
        if (kt + 1 < NT) {
            int nb = buf ^ 1;
            int k0a = ac * 4, k0b = (ac + 4) * 4;
            As[nb][k0a + 0][am] = ra0.x; As[nb][k0a + 1][am] = ra0.y;
            As[nb][k0a + 2][am] = ra0.z; As[nb][k0a + 3][am] = ra0.w;
            As[nb][k0b + 0][am] = ra1.x; As[nb][k0b + 1][am] = ra1.y;
            As[nb][k0b + 2][am] = ra1.z; As[nb][k0b + 3][am] = ra1.w;
            *(float4*)&Bs[nb][bk][bg * 8 + bp] = rb;
            __syncthreads();
            buf = nb;
        }
    }

    // scatter accumulators to smem for gate fusion
    {
        float v0, v1;
        unpack2(acc00, v0, v1); sm_a[2 * mi][ci * 4 + 0] = v0; sm_a[2 * mi][ci * 4 + 1] = v1;
        unpack2(acc01, v0, v1); sm_a[2 * mi][ci * 4 + 2] = v0; sm_a[2 * mi][ci * 4 + 3] = v1;
        unpack2(acc10, v0, v1); sm_a[2 * mi + 1][ci * 4 + 0] = v0; sm_a[2 * mi + 1][ci * 4 + 1] = v1;
        unpack2(acc11, v0, v1); sm_a[2 * mi + 1][ci * 4 + 2] = v0; sm_a[2 * mi + 1][ci * 4 + 3] = v1;
    }
    __syncthreads();

    // fused gates + state update: 512 (m, j) pairs, 2 per thread
    #pragma unroll
    for (int e = tid; e < 512; e += 256) {
        int m  = e >> 3;          // batch row 0..63
        int jj = e & 7;           // 0..7
        int j  = j0 + jj;         // 0..1023
        size_t xb = ((size_t)m * T_ + t) * G_ + j;
        float ai = sm_a[m][jj]       + g_xw[xb];
        float af = sm_a[m][8 + jj]   + g_xw[xb + 1024];
        float ao = sm_a[m][16 + jj]  + g_xw[xb + 2048];
        float ag = sm_a[m][24 + jj]  + g_xw[xb + 3072];
        float ig = sigmoidf_(ai);
        float fg = sigmoidf_(af);
        float og = sigmoidf_(ao);
        float gg = tanhf(ag);
        int hidx = m * H_ + j;
        float c = fg * g_c[hidx] + ig * gg;
        float h = og * tanhf(c);
        g_c[hidx]  = c;
        hout[hidx] = h;
        out[((size_t)m * T_ + t) * H_ + j] = h;
    }
}

// ---------------- launch ----------------
extern "C" void kernel_launch(void* const* d_in, const int* in_sizes, int n_in,
                              void* d_out, int out_size) {
    const float* x  = (const float*)d_in[0];   // (N, T, D)
    const float* h0 = (const float*)d_in[1];   // (N, H)
    const float* Wx = (const float*)d_in[2];   // (D, 4H)
    const float* Wh = (const float*)d_in[3];   // (H, 4H)
    const float* b  = (const float*)d_in[4];   // (4H,)
    float* out = (float*)d_out;                // (N, T, H)

    init_kernel<<<(N_ * H_ + 255) / 256, 256>>>(h0);

    dim3 gridA(G_ / 128, M_ / 128);            // (32, 256)
    gemm_xw_kernel<<<gridA, 256>>>(x, Wx, b);

    for (int t = 0; t < T_; t++) {
        lstm_step_kernel<<<H_ / 8, 256>>>(Wh, out, t, t & 1);
    }
}